// round 1
// baseline (speedup 1.0000x reference)
#include <cuda_runtime.h>

#define NU 50000
#define NI 50000
#define NN 100000   // NU + NI
#define D  64
#define K  4
#define E  1000000

// ---------------- scratch (device globals; no allocation allowed) ----------
__device__ float g_xc[NN * D];     // current x (chained across steps)
__device__ float g_g[NN * D];      // gather source  (dinv ⊙ h  /  dinv ⊙ edge)
__device__ float g_t[NN * D];      // scatter accumulator (A @ g)
__device__ float g_node[NN * D];   // node emb after softmax+fc1
__device__ float g_dinv[K * NN];   // per-subgraph D^-1/2 (degree first, then rsqrt)

// ---------------- degree / dinv --------------------------------------------
__global__ void count_deg_kernel(const int* __restrict__ rows,
                                 const int* __restrict__ cols) {
    int idx = blockIdx.x * blockDim.x + threadIdx.x;
    if (idx >= K * E) return;
    int k = idx / E;
    float* deg = g_dinv + k * NN;
    atomicAdd(deg + rows[idx], 1.0f);
    atomicAdd(deg + NU + cols[idx], 1.0f);
}

__global__ void finalize_dinv_kernel() {
    int idx = blockIdx.x * blockDim.x + threadIdx.x;
    if (idx < K * NN) g_dinv[idx] = rsqrtf(g_dinv[idx] + 1e-7f);
}

// ---------------- g = dinv ⊙ (relu(xc) + bias) ------------------------------
__global__ void compute_g_kernel(const float* __restrict__ bias, int k) {
    int idx = blockIdx.x * blockDim.x + threadIdx.x;
    if (idx >= NN * 16) return;
    int i = idx >> 4;
    int q = (idx & 15) << 2;
    float di = g_dinv[k * NN + i];
    float4 x = *(const float4*)(g_xc + i * D + q);
    float4 b = *(const float4*)(bias + q);
    float4 o;
    o.x = di * (fmaxf(x.x, 0.f) + b.x);
    o.y = di * (fmaxf(x.y, 0.f) + b.y);
    o.z = di * (fmaxf(x.z, 0.f) + b.z);
    o.w = di * (fmaxf(x.w, 0.f) + b.w);
    *(float4*)(g_g + i * D + q) = o;
}

// ---------------- t[src] += g[dst] over symmetric edges ---------------------
// One warp per interaction. Lanes 0-15 handle (r <- g[c]), lanes 16-31 (c <- g[r]).
// Each lane moves one float4 (16 lanes * 4 = 64 cols).
__global__ void spmm_kernel(const int* __restrict__ rows,
                            const int* __restrict__ cols) {
    int gw = (blockIdx.x * blockDim.x + threadIdx.x) >> 5;
    if (gw >= E) return;
    int lane = threadIdx.x & 31;
    int r = __ldg(rows + gw);
    int c = __ldg(cols + gw) + NU;
    int q   = (lane & 15) << 2;
    int src = (lane < 16) ? c : r;   // gather row
    int dst = (lane < 16) ? r : c;   // scatter row
    float4 v = *(const float4*)(g_g + src * D + q);
#if __CUDA_ARCH__ >= 900
    atomicAdd(reinterpret_cast<float4*>(g_t + dst * D + q), v);
#else
    float* p = g_t + dst * D + q;
    atomicAdd(p + 0, v.x); atomicAdd(p + 1, v.y);
    atomicAdd(p + 2, v.z); atomicAdd(p + 3, v.w);
#endif
}

// ---------------- edge = dinv ⊙ t (output), g = dinv ⊙ edge -----------------
__global__ void edge_g2_kernel(float* __restrict__ edge_out, int k) {
    int idx = blockIdx.x * blockDim.x + threadIdx.x;
    if (idx >= NN * 16) return;
    int i = idx >> 4;
    int q = (idx & 15) << 2;
    float di = g_dinv[k * NN + i];
    float4 t = *(const float4*)(g_t + i * D + q);
    float4 e = make_float4(di * t.x, di * t.y, di * t.z, di * t.w);
    *(float4*)(edge_out + (size_t)i * D + q) = e;
    *(float4*)(g_g + i * D + q) = make_float4(di * e.x, di * e.y, di * e.z, di * e.w);
}

// ---------------- node = softmax(dinv ⊙ t) @ fc1_W^T -------------------------
// One warp per row; fc1_W transposed into shared (Wt[d][j]) for conflict-free
// float2 reads; softmax row lives in shared per warp.
__global__ void softmax_fc1_kernel(const float* __restrict__ fc1_W, int k) {
    __shared__ float Wt[64 * 64];
    __shared__ float sm[8][64];
    int tid = threadIdx.x;
    for (int i = tid; i < 4096; i += 256) {
        int j = i >> 6, d = i & 63;
        Wt[d * 64 + j] = fc1_W[i];
    }
    __syncthreads();
    int warp = tid >> 5, lane = tid & 31;
    int row = blockIdx.x * 8 + warp;
    float di = g_dinv[k * NN + row];
    float2 v = *(const float2*)(g_t + row * D + lane * 2);
    v.x *= di; v.y *= di;
    float m = fmaxf(v.x, v.y);
#pragma unroll
    for (int o = 16; o; o >>= 1) m = fmaxf(m, __shfl_xor_sync(0xffffffffu, m, o));
    float e0 = __expf(v.x - m), e1 = __expf(v.y - m);
    float s = e0 + e1;
#pragma unroll
    for (int o = 16; o; o >>= 1) s += __shfl_xor_sync(0xffffffffu, s, o);
    float inv = 1.0f / s;
    sm[warp][lane * 2]     = e0 * inv;
    sm[warp][lane * 2 + 1] = e1 * inv;
    __syncwarp();
    float a0 = 0.f, a1 = 0.f;
    int j0 = lane * 2;
#pragma unroll
    for (int d = 0; d < 64; d++) {
        float sv = sm[warp][d];
        float2 w = *(const float2*)(&Wt[d * 64 + j0]);
        a0 += sv * w.x;
        a1 += sv * w.y;
    }
    *(float2*)(g_node + row * D + j0) = make_float2(a0, a1);
}

// ---------------- fusion gate: x_new = α·xc + (1-α)·node ---------------------
// score_e = w2 · tanh(W1 @ emb_e + b1)   (b2 cancels in the 2-way softmax)
__global__ void fusion_kernel(const float* __restrict__ W1,
                              const float* __restrict__ b1,
                              const float* __restrict__ w2,
                              float* __restrict__ out_nodes) {
    __shared__ float Wt[64 * 64];
    __shared__ float b1s[64];
    __shared__ float w2s[64];
    __shared__ float eX[8][64];
    __shared__ float eN[8][64];
    int tid = threadIdx.x;
    for (int i = tid; i < 4096; i += 256) {
        int j = i >> 6, d = i & 63;
        Wt[d * 64 + j] = W1[i];
    }
    if (tid < 64) { b1s[tid] = b1[tid]; w2s[tid] = w2[tid]; }
    __syncthreads();
    int warp = tid >> 5, lane = tid & 31;
    int row = blockIdx.x * 8 + warp;
    int j0 = lane * 2;
    float2 vx = *(const float2*)(g_xc   + row * D + j0);
    float2 vn = *(const float2*)(g_node + row * D + j0);
    eX[warp][j0] = vx.x; eX[warp][j0 + 1] = vx.y;
    eN[warp][j0] = vn.x; eN[warp][j0 + 1] = vn.y;
    __syncwarp();
    float ax0 = b1s[j0], ax1 = b1s[j0 + 1];
    float an0 = ax0,     an1 = ax1;
#pragma unroll
    for (int d = 0; d < 64; d++) {
        float2 w = *(const float2*)(&Wt[d * 64 + j0]);
        float ex = eX[warp][d], en = eN[warp][d];
        ax0 += ex * w.x; ax1 += ex * w.y;
        an0 += en * w.x; an1 += en * w.y;
    }
    float sx = tanhf(ax0) * w2s[j0] + tanhf(ax1) * w2s[j0 + 1];
    float sn = tanhf(an0) * w2s[j0] + tanhf(an1) * w2s[j0 + 1];
#pragma unroll
    for (int o = 16; o; o >>= 1) {
        sx += __shfl_xor_sync(0xffffffffu, sx, o);
        sn += __shfl_xor_sync(0xffffffffu, sn, o);
    }
    float m  = fmaxf(sx, sn);
    float e0 = __expf(sx - m), e1 = __expf(sn - m);
    float a  = e0 / (e0 + e1);
    float2 o2;
    o2.x = a * vx.x + (1.f - a) * vn.x;
    o2.y = a * vx.y + (1.f - a) * vn.y;
    *(float2*)(g_xc + row * D + j0)       = o2;  // chain into next step
    *(float2*)(out_nodes + (size_t)row * D + j0) = o2;
}

// ---------------- launch -----------------------------------------------------
extern "C" void kernel_launch(void* const* d_in, const int* in_sizes, int n_in,
                              void* d_out, int out_size) {
    const float* x         = (const float*)d_in[0];
    const float* hgc1_bias = (const float*)d_in[1];
    const float* fc1_W     = (const float*)d_in[2];
    const float* fus_l1_W  = (const float*)d_in[3];
    const float* fus_l1_b  = (const float*)d_in[4];
    const float* fus_l2_W  = (const float*)d_in[5];
    // d_in[6] = fus_l2_b : cancels in the 2-way softmax
    const int* rows = (const int*)d_in[7];
    const int* cols = (const int*)d_in[8];

    float* out_nodes = (float*)d_out;
    float* out_edges = (float*)d_out + (size_t)K * NN * D;

    float *xc_p = nullptr, *t_p = nullptr, *dinv_p = nullptr;
    cudaGetSymbolAddress((void**)&xc_p, g_xc);
    cudaGetSymbolAddress((void**)&t_p, g_t);
    cudaGetSymbolAddress((void**)&dinv_p, g_dinv);

    // degrees for all K subgraphs (independent of x)
    cudaMemsetAsync(dinv_p, 0, (size_t)K * NN * sizeof(float));
    count_deg_kernel<<<(K * E + 255) / 256, 256>>>(rows, cols);
    finalize_dinv_kernel<<<(K * NN + 255) / 256, 256>>>();

    cudaMemcpyAsync(xc_p, x, (size_t)NN * D * sizeof(float),
                    cudaMemcpyDeviceToDevice);

    const int ELT_BLOCKS  = (NN * 16 + 255) / 256;           // 6250
    const int SPMM_BLOCKS = (int)(((long long)E * 32) / 256); // 125000
    const int ROW_BLOCKS  = NN / 8;                           // 12500

    for (int k = 0; k < K; k++) {
        cudaMemsetAsync(t_p, 0, (size_t)NN * D * sizeof(float));
        compute_g_kernel<<<ELT_BLOCKS, 256>>>(hgc1_bias, k);
        spmm_kernel<<<SPMM_BLOCKS, 256>>>(rows + (size_t)k * E, cols + (size_t)k * E);
        edge_g2_kernel<<<ELT_BLOCKS, 256>>>(out_edges + (size_t)k * NN * D, k);
        cudaMemsetAsync(t_p, 0, (size_t)NN * D * sizeof(float));
        spmm_kernel<<<SPMM_BLOCKS, 256>>>(rows + (size_t)k * E, cols + (size_t)k * E);
        softmax_fc1_kernel<<<ROW_BLOCKS, 256>>>(fc1_W, k);
        fusion_kernel<<<ROW_BLOCKS, 256>>>(fus_l1_W, fus_l1_b, fus_l2_W,
                                           out_nodes + (size_t)k * NN * D);
    }
}

// round 3
// speedup vs baseline: 2.6488x; 2.6488x over previous
#include <cuda_runtime.h>

#define NU 50000
#define NI 50000
#define NN 100000            // NU + NI
#define D  64
#define K  4
#define E  1000000
#define NTOT (K * NN)        // 400000
#define TOTE (K * 2 * E)     // 8M directed edges
#define SCAN_CHUNK 1024
#define NB_SCAN ((NTOT + SCAN_CHUNK - 1) / SCAN_CHUNK)   // 391

// ---------------- device scratch (no allocation allowed) -------------------
__device__ int   g_deg[NTOT];        // per-subgraph degree counts
__device__ int   g_rowptr[NTOT + 1]; // CSR row pointers (global over K subgraphs)
__device__ int   g_cursor[NTOT];     // fill cursors
__device__ int   g_col[TOTE];        // CSR neighbor ids (node id 0..NN-1)
__device__ float g_dinv[NTOT];       // D^-1/2 per subgraph
__device__ float g_xc[NN * D];       // current x (chained across steps)
__device__ float g_g[NN * D];        // gather operand for each spmm
__device__ int   g_partials[NB_SCAN];

// ---------------- degree count ---------------------------------------------
__global__ void count_deg_kernel(const int* __restrict__ rows,
                                 const int* __restrict__ cols) {
    int idx = blockIdx.x * blockDim.x + threadIdx.x;
    if (idx >= K * E) return;
    int base = (idx / E) * NN;
    atomicAdd(g_deg + base + rows[idx], 1);
    atomicAdd(g_deg + base + NU + cols[idx], 1);
}

// ---------------- 3-kernel exclusive scan of g_deg --------------------------
__global__ void scan_s1_kernel() {
    __shared__ int red[256];
    int tid = threadIdx.x;
    int base = blockIdx.x * SCAN_CHUNK + tid * 4;
    int s = 0;
#pragma unroll
    for (int j = 0; j < 4; j++)
        if (base + j < NTOT) s += g_deg[base + j];
    red[tid] = s;
    __syncthreads();
    for (int off = 128; off; off >>= 1) {
        if (tid < off) red[tid] += red[tid + off];
        __syncthreads();
    }
    if (tid == 0) g_partials[blockIdx.x] = red[0];
}

__global__ void scan_s2_kernel() {
    __shared__ int sh[512];
    int tid = threadIdx.x;
    int v = (tid < NB_SCAN) ? g_partials[tid] : 0;
    sh[tid] = v;
    __syncthreads();
    for (int off = 1; off < 512; off <<= 1) {
        int t = (tid >= off) ? sh[tid - off] : 0;
        __syncthreads();
        sh[tid] += t;
        __syncthreads();
    }
    if (tid < NB_SCAN) g_partials[tid] = sh[tid] - v;   // exclusive
}

__global__ void scan_s3_kernel() {
    __shared__ int warp_sums[8];
    int tid = threadIdx.x;
    int lane = tid & 31, warp = tid >> 5;
    int base = blockIdx.x * SCAN_CHUNK + tid * 4;
    int e[4];
    int s = 0;
#pragma unroll
    for (int j = 0; j < 4; j++) {
        e[j] = (base + j < NTOT) ? g_deg[base + j] : 0;
        s += e[j];
    }
    int incl = s;
#pragma unroll
    for (int off = 1; off < 32; off <<= 1) {
        int t = __shfl_up_sync(0xffffffffu, incl, off);
        if (lane >= off) incl += t;
    }
    if (lane == 31) warp_sums[warp] = incl;
    __syncthreads();
    if (warp == 0 && lane < 8) {
        int v = warp_sums[lane];
        int iv = v;
#pragma unroll
        for (int off = 1; off < 8; off <<= 1) {
            int t = __shfl_up_sync(0xffu, iv, off);
            if (lane >= off) iv += t;
        }
        warp_sums[lane] = iv - v;   // exclusive within block
    }
    __syncthreads();
    int run = g_partials[blockIdx.x] + warp_sums[warp] + (incl - s);
#pragma unroll
    for (int j = 0; j < 4; j++) {
        int idx = base + j;
        if (idx < NTOT) {
            g_rowptr[idx] = run;
            g_cursor[idx] = run;
            g_dinv[idx]   = rsqrtf((float)e[j] + 1e-7f);
            run += e[j];
        }
    }
    if (blockIdx.x == 0 && tid == 0) g_rowptr[NTOT] = TOTE;
}

// ---------------- CSR fill ---------------------------------------------------
__global__ void fill_csr_kernel(const int* __restrict__ rows,
                                const int* __restrict__ cols) {
    int idx = blockIdx.x * blockDim.x + threadIdx.x;
    if (idx >= K * E) return;
    int base = (idx / E) * NN;
    int r = rows[idx];
    int c = cols[idx];
    int p1 = atomicAdd(g_cursor + base + r, 1);
    g_col[p1] = NU + c;
    int p2 = atomicAdd(g_cursor + base + NU + c, 1);
    g_col[p2] = r;
}

// ---------------- g = dinv ⊙ (relu(xc) + bias) -------------------------------
__global__ void compute_g_kernel(const float* __restrict__ bias, int k) {
    int idx = blockIdx.x * blockDim.x + threadIdx.x;
    if (idx >= NN * 16) return;
    int i = idx >> 4;
    int q = (idx & 15) << 2;
    float di = g_dinv[k * NN + i];
    float4 x = *(const float4*)(g_xc + i * D + q);
    float4 b = *(const float4*)(bias + q);
    float4 o;
    o.x = di * (fmaxf(x.x, 0.f) + b.x);
    o.y = di * (fmaxf(x.y, 0.f) + b.y);
    o.z = di * (fmaxf(x.z, 0.f) + b.z);
    o.w = di * (fmaxf(x.w, 0.f) + b.w);
    *(float4*)(g_g + i * D + q) = o;
}

// ---------------- spmm1: edge[i] = dinv[i] * sum_{n in N(i)} g[n] -------------
// Also writes g_g[i] = dinv[i] * edge[i] (gather operand of spmm2).
// One warp per row, gather from CSR, no atomics.
__global__ void spmm1_kernel(float* __restrict__ edge_out, int k) {
    int gw = (blockIdx.x * blockDim.x + threadIdx.x) >> 5;
    if (gw >= NN) return;
    int lane = threadIdx.x & 31;
    int lane2 = lane * 2;
    int rp = k * NN + gw;
    int beg = g_rowptr[rp], end = g_rowptr[rp + 1];
    float ax = 0.f, ay = 0.f;
    int p = beg;
    for (; p + 4 <= end; p += 4) {
        int n0 = __ldg(g_col + p);
        int n1 = __ldg(g_col + p + 1);
        int n2 = __ldg(g_col + p + 2);
        int n3 = __ldg(g_col + p + 3);
        float2 v0 = *(const float2*)(g_g + n0 * D + lane2);
        float2 v1 = *(const float2*)(g_g + n1 * D + lane2);
        float2 v2 = *(const float2*)(g_g + n2 * D + lane2);
        float2 v3 = *(const float2*)(g_g + n3 * D + lane2);
        ax += (v0.x + v1.x) + (v2.x + v3.x);
        ay += (v0.y + v1.y) + (v2.y + v3.y);
    }
    for (; p < end; p++) {
        int n = __ldg(g_col + p);
        float2 v = *(const float2*)(g_g + n * D + lane2);
        ax += v.x;
        ay += v.y;
    }
    float di = g_dinv[rp];
    float ex = di * ax, ey = di * ay;
    *(float2*)(edge_out + (size_t)gw * D + lane2) = make_float2(ex, ey);
    // NOTE: must not write g_g before all warps finished reading it -> use a
    // separate buffer? No: every row's gather reads OTHER rows' g_g entries and
    // rows are processed concurrently. Writing g_g here would race. Instead we
    // defer: write to g_g2 (aliased below via second half trick is unsafe), so
    // we keep a dedicated second kernel-free approach: store di*edge into the
    // edge row itself is WRONG too. We therefore write into g_gnext.
    // (see g_gnext definition)
    extern __device__ float g_gnext[];
    *(float2*)(g_gnext + (size_t)gw * D + lane2) = make_float2(di * ex, di * ey);
}

__device__ float g_gnext[NN * D];    // dinv ⊙ edge  (spmm2 gather operand)

// ---------------- tanh via HW approx ----------------------------------------
__device__ __forceinline__ float tanhf_fast(float x) {
    float y;
    asm("tanh.approx.f32 %0, %1;" : "=f"(y) : "f"(x));
    return y;
}

// ---------------- mega: spmm2 + softmax + fc1 + fusion gate ------------------
// Persistent-ish: weights loaded once per block; warp per row, grid-stride.
__global__ void __launch_bounds__(256)
mega_kernel(const float* __restrict__ fc1_W,
            const float* __restrict__ W1,
            const float* __restrict__ b1,
            const float* __restrict__ w2,
            float* __restrict__ out_nodes, int k) {
    __shared__ float Wt1[64 * 64];   // fc1 transposed: Wt1[d*64+j] = fc1_W[j][d]
    __shared__ float Wtf[64 * 64];   // fus_l1 transposed
    __shared__ float b1s[64], w2s[64];
    __shared__ float smv[8][64];     // softmax row per warp
    __shared__ float xb[8][64];      // xc row per warp
    __shared__ float nb[8][64];      // node row per warp

    int tid = threadIdx.x;
    for (int i = tid; i < 4096; i += 256) {
        int d = i >> 6, j = i & 63;
        Wt1[i] = fc1_W[j * 64 + d];   // conflict-free STS (consecutive addr)
        Wtf[i] = W1[j * 64 + d];
    }
    if (tid < 64) { b1s[tid] = b1[tid]; w2s[tid] = w2[tid]; }
    __syncthreads();

    int warp = tid >> 5, lane = tid & 31;
    int lane2 = lane * 2;

    for (int row = blockIdx.x * 8 + warp; row < NN; row += gridDim.x * 8) {
        // ---- spmm2 gather: node_pre = dinv[i] * sum g_gnext[n] ----
        int rp = k * NN + row;
        int beg = g_rowptr[rp], end = g_rowptr[rp + 1];
        float ax = 0.f, ay = 0.f;
        int p = beg;
        for (; p + 4 <= end; p += 4) {
            int n0 = __ldg(g_col + p);
            int n1 = __ldg(g_col + p + 1);
            int n2 = __ldg(g_col + p + 2);
            int n3 = __ldg(g_col + p + 3);
            float2 v0 = *(const float2*)(g_gnext + (size_t)n0 * D + lane2);
            float2 v1 = *(const float2*)(g_gnext + (size_t)n1 * D + lane2);
            float2 v2 = *(const float2*)(g_gnext + (size_t)n2 * D + lane2);
            float2 v3 = *(const float2*)(g_gnext + (size_t)n3 * D + lane2);
            ax += (v0.x + v1.x) + (v2.x + v3.x);
            ay += (v0.y + v1.y) + (v2.y + v3.y);
        }
        for (; p < end; p++) {
            int n = __ldg(g_col + p);
            float2 v = *(const float2*)(g_gnext + (size_t)n * D + lane2);
            ax += v.x;
            ay += v.y;
        }
        float di = g_dinv[rp];
        ax *= di;
        ay *= di;

        // ---- softmax over 64 (2 per lane) ----
        float m = fmaxf(ax, ay);
#pragma unroll
        for (int o = 16; o; o >>= 1) m = fmaxf(m, __shfl_xor_sync(0xffffffffu, m, o));
        float e0 = __expf(ax - m), e1 = __expf(ay - m);
        float ssum = e0 + e1;
#pragma unroll
        for (int o = 16; o; o >>= 1) ssum += __shfl_xor_sync(0xffffffffu, ssum, o);
        float inv = 1.0f / ssum;
        smv[warp][lane2]     = e0 * inv;
        smv[warp][lane2 + 1] = e1 * inv;

        float2 vx = *(const float2*)(g_xc + (size_t)row * D + lane2);
        xb[warp][lane2]     = vx.x;
        xb[warp][lane2 + 1] = vx.y;
        __syncwarp();

        // ---- fc1: node[j] = sum_d sm[d] * W[j][d] ----
        float n0 = 0.f, n1 = 0.f;
#pragma unroll
        for (int d = 0; d < 64; d++) {
            float sv = smv[warp][d];
            float2 w = *(const float2*)(&Wt1[d * 64 + lane2]);
            n0 += sv * w.x;
            n1 += sv * w.y;
        }
        nb[warp][lane2]     = n0;
        nb[warp][lane2 + 1] = n1;
        __syncwarp();

        // ---- fusion gate ----
        float ax0 = b1s[lane2], ax1 = b1s[lane2 + 1];
        float an0 = ax0, an1 = ax1;
#pragma unroll
        for (int d = 0; d < 64; d++) {
            float2 w = *(const float2*)(&Wtf[d * 64 + lane2]);
            float ex = xb[warp][d], en = nb[warp][d];
            ax0 += ex * w.x;
            ax1 += ex * w.y;
            an0 += en * w.x;
            an1 += en * w.y;
        }
        float sx = tanhf_fast(ax0) * w2s[lane2] + tanhf_fast(ax1) * w2s[lane2 + 1];
        float sn = tanhf_fast(an0) * w2s[lane2] + tanhf_fast(an1) * w2s[lane2 + 1];
#pragma unroll
        for (int o = 16; o; o >>= 1) {
            sx += __shfl_xor_sync(0xffffffffu, sx, o);
            sn += __shfl_xor_sync(0xffffffffu, sn, o);
        }
        float mm = fmaxf(sx, sn);
        float q0 = __expf(sx - mm), q1 = __expf(sn - mm);
        float a = q0 / (q0 + q1);

        float o0 = a * vx.x + (1.f - a) * n0;
        float o1 = a * vx.y + (1.f - a) * n1;
        *(float2*)(out_nodes + (size_t)row * D + lane2) = make_float2(o0, o1);
        *(float2*)(g_xc + (size_t)row * D + lane2)      = make_float2(o0, o1);
    }
}

// ---------------- launch ------------------------------------------------------
extern "C" void kernel_launch(void* const* d_in, const int* in_sizes, int n_in,
                              void* d_out, int out_size) {
    const float* x         = (const float*)d_in[0];
    const float* hgc1_bias = (const float*)d_in[1];
    const float* fc1_W     = (const float*)d_in[2];
    const float* fus_l1_W  = (const float*)d_in[3];
    const float* fus_l1_b  = (const float*)d_in[4];
    const float* fus_l2_W  = (const float*)d_in[5];
    // d_in[6] = fus_l2_b : cancels in the 2-way softmax
    const int* rows = (const int*)d_in[7];
    const int* cols = (const int*)d_in[8];

    float* out_nodes = (float*)d_out;
    float* out_edges = (float*)d_out + (size_t)K * NN * D;

    float* xc_p = nullptr;
    int* deg_p = nullptr;
    cudaGetSymbolAddress((void**)&xc_p, g_xc);
    cudaGetSymbolAddress((void**)&deg_p, g_deg);

    // CSR build (depends only on rows/cols)
    cudaMemsetAsync(deg_p, 0, (size_t)NTOT * sizeof(int));
    count_deg_kernel<<<(K * E + 255) / 256, 256>>>(rows, cols);
    scan_s1_kernel<<<NB_SCAN, 256>>>();
    scan_s2_kernel<<<1, 512>>>();
    scan_s3_kernel<<<NB_SCAN, 256>>>();
    fill_csr_kernel<<<(K * E + 255) / 256, 256>>>(rows, cols);

    cudaMemcpyAsync(xc_p, x, (size_t)NN * D * sizeof(float),
                    cudaMemcpyDeviceToDevice);

    const int ELT_BLOCKS  = (NN * 16 + 255) / 256;  // 6250
    const int SPMM_BLOCKS = NN / 8;                  // 12500 (warp per row)
    const int MEGA_BLOCKS = 740;

    for (int k = 0; k < K; k++) {
        float* edge_k = out_edges + (size_t)k * NN * D;
        compute_g_kernel<<<ELT_BLOCKS, 256>>>(hgc1_bias, k);
        spmm1_kernel<<<SPMM_BLOCKS, 256>>>(edge_k, k);
        mega_kernel<<<MEGA_BLOCKS, 256>>>(fc1_W, fus_l1_W, fus_l1_b, fus_l2_W,
                                          out_nodes + (size_t)k * NN * D, k);
    }
}